// round 16
// baseline (speedup 1.0000x reference)
#include <cuda_runtime.h>
#include <cuda_fp16.h>

#define FULLMASK 0xffffffffu
constexpr int B_ = 4, C_ = 128, N_ = 4096, K_ = 16;
constexpr int BN_ = B_ * N_;
constexpr int LD_ = 132;
constexpr int WST = 136;   // fp16 smem row stride (elems)
constexpr int FST = 132;   // fp32 smem row stride (elems)

__device__ float g_Ttop[C_*C_], g_TE[C_*C_], g_TF[C_*C_], g_Tal[C_*C_],
                 g_TG[C_*C_], g_Tdn[C_*C_];
__device__ float g_bE[C_], g_bF[C_], g_c0v[C_];
__device__ float g_x[BN_*C_];     // [B][C][N]
__device__ float g_E[BN_*C_];     // [B][N][C]
__device__ float g_F[BN_*C_];     // [B][N][C]
__device__ float g_alp[BN_*C_];   // [B][N][C]
__device__ float g_y[BN_*C_];     // [B][N][C]
__device__ int   g_idx[BN_*K_];
// MMA-fragment-layout fp16-split weights: [mat 0=d2,1=G,2=g2][hi/lo][co_tile][kstep][lane]
__device__ uint4 g_Wfr[3][2][8][8][32];

// ---------------- helpers ----------------
__device__ __forceinline__ unsigned smem_u32(const void* p) {
    unsigned a;
    asm("{ .reg .u64 t; cvta.to.shared.u64 t, %1; cvt.u32.u64 %0, t; }" : "=r"(a) : "l"(p));
    return a;
}
__device__ __forceinline__ void ldsm4(unsigned addr, unsigned r[4]) {
    asm volatile("ldmatrix.sync.aligned.m8n8.x4.shared.b16 {%0,%1,%2,%3}, [%4];"
        : "=r"(r[0]), "=r"(r[1]), "=r"(r[2]), "=r"(r[3]) : "r"(addr));
}
__device__ __forceinline__ void mma_f16(float c[4], unsigned a0, unsigned a1,
    unsigned a2, unsigned a3, unsigned b0, unsigned b1) {
    asm volatile("mma.sync.aligned.m16n8k16.row.col.f32.f16.f16.f32 "
        "{%0,%1,%2,%3},{%4,%5,%6,%7},{%8,%9},{%0,%1,%2,%3};"
        : "+f"(c[0]), "+f"(c[1]), "+f"(c[2]), "+f"(c[3])
        : "r"(a0), "r"(a1), "r"(a2), "r"(a3), "r"(b0), "r"(b1));
}
__device__ __forceinline__ unsigned short hfb(float v) {
    __half h = __float2half(v);
    return *reinterpret_cast<unsigned short*>(&h);
}

// 2-pass fp16 split sweep: acc[8][4] += W(16co x 128k) * B(64m x 128k)^T
__device__ __forceinline__ void gemm2_sweep(const uint4* __restrict__ Wh,
    const uint4* __restrict__ Wl, unsigned Bh, float acc[8][4], int lane)
{
    uint4 ah[8], al[8];
#pragma unroll
    for (int ks = 0; ks < 8; ks++) { ah[ks] = Wh[ks*32 + lane]; al[ks] = Wl[ks*32 + lane]; }
    int lr = lane & 7, sel = lane >> 3;
    int bro = lr + (((sel >> 1) & 1) << 3);
    int bco = (sel & 1) << 3;
#pragma unroll
    for (int ks = 0; ks < 8; ks++) {
        int k0 = ks * 16;
#pragma unroll
        for (int jp = 0; jp < 4; jp++) {
            unsigned boff = (unsigned)(((jp*16 + bro)*WST + bco + k0) << 1);
            unsigned bh[4];
            ldsm4(Bh + boff, bh);
            mma_f16(acc[2*jp],   ah[ks].x, ah[ks].y, ah[ks].z, ah[ks].w, bh[0], bh[1]);
            mma_f16(acc[2*jp+1], ah[ks].x, ah[ks].y, ah[ks].z, ah[ks].w, bh[2], bh[3]);
            mma_f16(acc[2*jp],   al[ks].x, al[ks].y, al[ks].z, al[ks].w, bh[0], bh[1]);
            mma_f16(acc[2*jp+1], al[ks].x, al[ks].y, al[ks].z, al[ks].w, bh[2], bh[3]);
        }
    }
}

// Dual 2-pass sweep: two weight matrices share each B-fragment load.
__device__ __forceinline__ void gemm2_dual(
    const uint4* __restrict__ W0h, const uint4* __restrict__ W0l,
    const uint4* __restrict__ W1h, const uint4* __restrict__ W1l,
    unsigned Bh, float accA[8][4], float accB[8][4], int lane)
{
    int lr = lane & 7, sel = lane >> 3;
    int bro = lr + (((sel >> 1) & 1) << 3);
    int bco = (sel & 1) << 3;
#pragma unroll
    for (int ks = 0; ks < 8; ks++) {
        uint4 a0 = W0h[ks*32 + lane], l0 = W0l[ks*32 + lane];
        uint4 a1 = W1h[ks*32 + lane], l1 = W1l[ks*32 + lane];
        int k0 = ks * 16;
#pragma unroll
        for (int jp = 0; jp < 4; jp++) {
            unsigned boff = (unsigned)(((jp*16 + bro)*WST + bco + k0) << 1);
            unsigned bh[4];
            ldsm4(Bh + boff, bh);
            mma_f16(accA[2*jp],   a0.x, a0.y, a0.z, a0.w, bh[0], bh[1]);
            mma_f16(accA[2*jp+1], a0.x, a0.y, a0.z, a0.w, bh[2], bh[3]);
            mma_f16(accB[2*jp],   a1.x, a1.y, a1.z, a1.w, bh[0], bh[1]);
            mma_f16(accB[2*jp+1], a1.x, a1.y, a1.z, a1.w, bh[2], bh[3]);
            mma_f16(accA[2*jp],   l0.x, l0.y, l0.z, l0.w, bh[0], bh[1]);
            mma_f16(accA[2*jp+1], l0.x, l0.y, l0.z, l0.w, bh[2], bh[3]);
            mma_f16(accB[2*jp],   l1.x, l1.y, l1.z, l1.w, bh[0], bh[1]);
            mma_f16(accB[2*jp+1], l1.x, l1.y, l1.z, l1.w, bh[2], bh[3]);
        }
    }
}

// ---- prep1: transpose / fuse fp32 weights ----
__global__ __launch_bounds__(256) void prep_kernel(
    const float* __restrict__ topW, const float* __restrict__ phiW,
    const float* __restrict__ psiW, const float* __restrict__ alW,
    const float* __restrict__ g2W,  const float* __restrict__ dnW,
    const float* __restrict__ d2W,  const float* __restrict__ g1W,
    const float* __restrict__ phiB, const float* __restrict__ psiB,
    const float* __restrict__ d2B,  const float* __restrict__ g1B)
{
    int s = blockIdx.x, tid = threadIdx.x;
    if (s == 0 || s == 3 || s == 7) {
        const float* src = (s==0)?topW : (s==3)?alW : dnW;
        float* dst       = (s==0)?g_Ttop : (s==3)?g_Tal : g_Tdn;
        for (int q = tid; q < C_*C_; q += 256) {
            int co = q >> 7, ci = q & 127;
            dst[ci*C_ + co] = src[co*C_ + ci];
        }
    } else if (s == 1 || s == 2 || s == 5) {
        const float* rW = (s==1)?phiW : (s==2)?psiW : d2W;
        float* dst      = (s==1)?g_TE : (s==2)?g_TF : g_TG;
        for (int q = tid; q < C_*C_; q += 256) {
            int co = q >> 7, ci = q & 127;
            float a = 0.f;
            for (int m = 0; m < C_; m++) a = fmaf(g1W[co*C_+m], rW[m*C_+ci], a);
            dst[ci*C_ + co] = a;
        }
        if (tid < C_) {
            const float* rb = (s==1)?phiB : (s==2)?psiB : d2B;
            float a = 0.f;
            for (int m = 0; m < C_; m++) a = fmaf(g1W[tid*C_+m], rb[m], a);
            if (s==1) g_bE[tid] = a;
            else if (s==2) g_bF[tid] = a;
            else g_c0v[tid] = a + g1B[tid];
        }
    }
}

// ---- prep2: build fragment-layout fp16-split weights (after prep1) ----
__global__ __launch_bounds__(256) void prep2_kernel(
    const float* __restrict__ d2W, const float* __restrict__ g2W)
{
    int s = blockIdx.x, tid = threadIdx.x;
    for (int q = tid; q < 2048; q += 256) {
        int t = q >> 8, ks = (q >> 5) & 7, lane = q & 31;
        int g = lane >> 2, c2 = (lane & 3) * 2;
        int r0 = t*16 + g, r1 = r0 + 8;
        int c0 = ks*16 + c2;
        unsigned hi[4], lo[4];
#pragma unroll
        for (int e = 0; e < 4; e++) {
            int rr = (e & 1) ? r1 : r0;
            int cb = c0 + ((e >> 1) << 3);
            float vA = (s==0) ? d2W[rr*C_+cb]     : (s==1) ? g_TG[cb*C_+rr]     : g2W[rr*C_+cb];
            float vB = (s==0) ? d2W[rr*C_+cb+1]   : (s==1) ? g_TG[(cb+1)*C_+rr] : g2W[rr*C_+cb+1];
            hi[e] = ((unsigned)hfb(vB) << 16) | (unsigned)hfb(vA);
            float ra = vA - __half2float(__float2half(vA));
            float rb2 = vB - __half2float(__float2half(vB));
            lo[e] = ((unsigned)hfb(rb2) << 16) | (unsigned)hfb(ra);
        }
        g_Wfr[s][0][t][ks][lane] = make_uint4(hi[0], hi[1], hi[2], hi[3]);
        g_Wfr[s][1][t][ks][lane] = make_uint4(lo[0], lo[1], lo[2], lo[3]);
    }
}

// ---- KNN: 1 warp per query point ----
__global__ __launch_bounds__(256) void knn_kernel(const float* __restrict__ p)
{
    extern __shared__ float sm[];
    float* px = sm;      float* py = px + N_;
    float* pz = py + N_; float* sq = pz + N_;
    float* md = sq + N_;
    int*   mi = (int*)(md + 8*512);

    int b = blockIdx.y;
    const float* pb = p + (size_t)b*3*N_;
    for (int i = threadIdx.x; i < N_; i += 256) {
        float x = pb[i], y = pb[N_+i], z = pb[2*N_+i];
        px[i]=x; py[i]=y; pz[i]=z;
        sq[i] = __fadd_rn(__fadd_rn(__fmul_rn(x,x), __fmul_rn(y,y)), __fmul_rn(z,z));
    }
    __syncthreads();

    int warp = threadIdx.x >> 5, lane = threadIdx.x & 31;
    int n = blockIdx.x*8 + warp;
    float qx=px[n], qy=py[n], qz=pz[n], qs=sq[n];

    float bd[16]; int bi[16];
#pragma unroll
    for (int t=0;t<16;t++){ bd[t]=3.4e38f; bi[t]=0; }
    for (int c = lane; c < N_; c += 32) {
        float dot = __fadd_rn(__fadd_rn(__fmul_rn(qx,px[c]), __fmul_rn(qy,py[c])), __fmul_rn(qz,pz[c]));
        float d = __fadd_rn(__fadd_rn(qs, sq[c]), __fmul_rn(-2.f, dot));
        if (d < bd[15]) {
            bd[15]=d; bi[15]=c;
#pragma unroll
            for (int t=15;t>0;--t)
                if (bd[t] < bd[t-1]) {
                    float tf=bd[t]; bd[t]=bd[t-1]; bd[t-1]=tf;
                    int ti=bi[t]; bi[t]=bi[t-1]; bi[t-1]=ti;
                }
        }
    }
    float* wd = md + warp*512; int* wi = mi + warp*512;
#pragma unroll
    for (int t=0;t<16;t++){ wd[lane*16+t]=bd[t]; wi[lane*16+t]=bi[t]; }
    __syncwarp();

    int ptr = 0;
    int* outp = g_idx + ((size_t)b*N_ + n)*K_;
    for (int r = 0; r < K_; r++) {
        float cd = (ptr<16) ? wd[lane*16+ptr] : 3.4e38f;
        int   ci = (ptr<16) ? wi[lane*16+ptr] : 0;
        float mdv = cd; int miv = ci; int ml = lane;
#pragma unroll
        for (int off=16; off>0; off>>=1) {
            float od = __shfl_down_sync(FULLMASK, mdv, off);
            int   oi = __shfl_down_sync(FULLMASK, miv, off);
            int   ol = __shfl_down_sync(FULLMASK, ml,  off);
            if (od < mdv) { mdv=od; miv=oi; ml=ol; }
        }
        miv = __shfl_sync(FULLMASK, miv, 0);
        ml  = __shfl_sync(FULLMASK, ml, 0);
        if (lane == ml) ptr++;
        if (lane == 0) outp[r] = miv;
    }
}

// ---- fp32 GEMM fragment (weights in SMEM) ----
__device__ __forceinline__ void gemm_frag(const float* __restrict__ WT,
    const float* __restrict__ S, int c0, int m0, float acc[8][8])
{
#pragma unroll 4
    for (int ci = 0; ci < C_; ci++) {
        float4 a0 = *reinterpret_cast<const float4*>(WT + ci*C_ + c0);
        float4 a1 = *reinterpret_cast<const float4*>(WT + ci*C_ + c0 + 4);
        float4 b0 = *reinterpret_cast<const float4*>(S + ci*LD_ + m0);
        float4 b1 = *reinterpret_cast<const float4*>(S + ci*LD_ + m0 + 4);
        float av[8] = {a0.x,a0.y,a0.z,a0.w,a1.x,a1.y,a1.z,a1.w};
        float bv[8] = {b0.x,b0.y,b0.z,b0.w,b1.x,b1.y,b1.z,b1.w};
#pragma unroll
        for (int i=0;i<8;i++)
#pragma unroll
            for (int j=0;j<8;j++) acc[i][j] = fmaf(av[i], bv[j], acc[i][j]);
    }
}

// SLOT: 0 top  4 down(+residual)
template<int SLOT>
__global__ __launch_bounds__(256) void gemm_point(
    const float* __restrict__ ext_bias, const float* __restrict__ ext_in,
    float* __restrict__ ext_out, const float* __restrict__ resid)
{
    extern __shared__ float Hs[];
    float* Ws = Hs + 128*LD_;
    int b = blockIdx.y, n0 = blockIdx.x*128, tid = threadIdx.x;
    const float* WT = (SLOT==0)?g_Ttop : g_Tdn;
    const float* in = (SLOT==0)?ext_in : g_y;
    const float* bias = ext_bias;

    for (int q = tid; q < 16384; q += 256) Ws[q] = WT[q];
    if (SLOT == 4) {
        for (int q = tid; q < 4096; q += 256) {
            int m = q >> 5, c4 = q & 31;
            float4 v = *reinterpret_cast<const float4*>(in + ((size_t)(b*N_)+n0+m)*C_ + c4*4);
            int c = c4*4;
            Hs[(c+0)*LD_+m]=v.x; Hs[(c+1)*LD_+m]=v.y; Hs[(c+2)*LD_+m]=v.z; Hs[(c+3)*LD_+m]=v.w;
        }
    } else {
        for (int q = tid; q < 4096; q += 256) {
            int ci = q >> 5, m4 = q & 31;
            float4 v = *reinterpret_cast<const float4*>(in + ((size_t)(b*C_)+ci)*N_ + n0 + m4*4);
            *reinterpret_cast<float4*>(Hs + ci*LD_ + m4*4) = v;
        }
    }
    __syncthreads();

    int tx = tid & 15, ty = tid >> 4;
    int m0 = tx*8, c0 = ty*8;
    float acc[8][8];
#pragma unroll
    for (int i=0;i<8;i++)
#pragma unroll
        for (int j=0;j<8;j++) acc[i][j] = 0.f;
    gemm_frag(Ws, Hs, c0, m0, acc);

    float bs[8];
#pragma unroll
    for (int i=0;i<8;i++) bs[i] = bias[c0+i];

    float* outp = (SLOT==0) ? g_x : ext_out;
#pragma unroll
    for (int i=0;i<8;i++) {
        int c = c0+i;
        float v[8];
#pragma unroll
        for (int j=0;j<8;j++) v[j] = acc[i][j] + bs[i];
        if (SLOT == 4) {
            const float* r = resid + ((size_t)(b*C_)+c)*N_ + n0 + m0;
#pragma unroll
            for (int j=0;j<8;j++) v[j] += r[j];
        }
        float4 o0 = {v[0],v[1],v[2],v[3]}, o1 = {v[4],v[5],v[6],v[7]};
        *reinterpret_cast<float4*>(outp + ((size_t)(b*C_)+c)*N_ + n0 + m0)     = o0;
        *reinterpret_cast<float4*>(outp + ((size_t)(b*C_)+c)*N_ + n0 + m0 + 4) = o1;
    }
}

// merged E/F/alpha GEMMs: slot = blockIdx.z (0=E,1=F,2=alpha), in = g_x, out [B][N][C]
__global__ __launch_bounds__(256) void gemm_point123(const float* __restrict__ alB)
{
    extern __shared__ float Hs[];
    float* Ws = Hs + 128*LD_;
    int b = blockIdx.y, n0 = blockIdx.x*128, tid = threadIdx.x;
    int slot = blockIdx.z;
    const float* WT   = (slot==0)?g_TE : (slot==1)?g_TF : g_Tal;
    const float* bias = (slot==0)?g_bE : (slot==1)?g_bF : alB;
    float* outp       = (slot==0)?g_E  : (slot==1)?g_F  : g_alp;

    for (int q = tid; q < 16384; q += 256) Ws[q] = WT[q];
    for (int q = tid; q < 4096; q += 256) {
        int ci = q >> 5, m4 = q & 31;
        float4 v = *reinterpret_cast<const float4*>(g_x + ((size_t)(b*C_)+ci)*N_ + n0 + m4*4);
        *reinterpret_cast<float4*>(Hs + ci*LD_ + m4*4) = v;
    }
    __syncthreads();

    int tx = tid & 15, ty = tid >> 4;
    int m0 = tx*8, c0 = ty*8;
    float acc[8][8];
#pragma unroll
    for (int i=0;i<8;i++)
#pragma unroll
        for (int j=0;j<8;j++) acc[i][j] = 0.f;
    gemm_frag(Ws, Hs, c0, m0, acc);

    float bs[8];
#pragma unroll
    for (int i=0;i<8;i++) bs[i] = bias[c0+i];
#pragma unroll
    for (int j=0;j<8;j++) {
        int m = m0+j;
        float4 o0 = {acc[0][j]+bs[0], acc[1][j]+bs[1], acc[2][j]+bs[2], acc[3][j]+bs[3]};
        float4 o1 = {acc[4][j]+bs[4], acc[5][j]+bs[5], acc[6][j]+bs[6], acc[7][j]+bs[7]};
        *reinterpret_cast<float4*>(outp + ((size_t)(b*N_)+n0+m)*C_ + c0)     = o0;
        *reinterpret_cast<float4*>(outp + ((size_t)(b*N_)+n0+m)*C_ + c0 + 4) = o1;
    }
}

// ---- heavy kernel: 4 pts x 16 nbrs per CTA, 8 warps, 2 CTAs/SM ----
constexpr int OFF_HH = 0;                      // 64*WST*2 = 17408 (fp16 H/T)
constexpr int OFF_FS = 17408;                  // 64*FST*4 = 33792 (F, then alp)
constexpr int OFF_PS = 51200;                  // 33792 (pos)
constexpr int OFF_ES = 84992;                  // 4*128*4 = 2048
constexpr int OFF_RX = 87040;                  // 3*64*4
constexpr int OFF_JB = 87808;                  // 64*4
constexpr int HEAVY_SMEM = 88064;

__global__ __launch_bounds__(256, 2) void heavy_kernel(
    const float* __restrict__ p, const float* __restrict__ d1W,
    const float* __restrict__ d1B, const float* __restrict__ d2B,
    const float* __restrict__ g2B)
{
    extern __shared__ char smc[];
    unsigned sbase = smem_u32(smc);
    __half* Hh = (__half*)(smc + OFF_HH);
    float* Fsm = (float*)(smc + OFF_FS);
    float* Ps  = (float*)(smc + OFF_PS);
    float* EsS = (float*)(smc + OFF_ES);
    float* rx = (float*)(smc + OFF_RX);
    float* ry = rx + 64; float* rz = ry + 64;
    int*   jb = (int*)(smc + OFF_JB);

    int b = blockIdx.y, pt0 = blockIdx.x*4, tid = threadIdx.x;
    int lane = tid & 31, w = tid >> 5;
    size_t bN = (size_t)b * N_;

    const float* pb = p + (size_t)b*3*N_;
    if (tid < 64) {
        int m = tid, pt = m >> 4, n = pt0 + pt;
        int j = g_idx[(bN + n)*K_ + (m & 15)];
        jb[m] = j;
        rx[m] = pb[n]      - pb[j];
        ry[m] = pb[N_+n]   - pb[N_+j];
        rz[m] = pb[2*N_+n] - pb[2*N_+j];
    }
    for (int q = tid; q < 512; q += 256)
        EsS[q] = g_E[(bN + pt0 + (q >> 7))*C_ + (q & 127)];
    __syncthreads();

    // H build (single fp16) + F gather
    for (int q = tid; q < 8192; q += 256) {
        int m = q >> 7, ci = q & 127;
        float h = fmaf(d1W[ci*3+2], rz[m],
                  fmaf(d1W[ci*3+1], ry[m],
                  fmaf(d1W[ci*3+0], rx[m], d1B[ci])));
        Hh[m*WST + ci] = __float2half(fmaxf(h, 0.f));
    }
    for (int q = tid; q < 2048; q += 256) {
        int m = q >> 5, c4 = q & 31;
        float4 v = *reinterpret_cast<const float4*>(g_F + (bN + jb[m])*C_ + c4*4);
        *reinterpret_cast<float4*>(Fsm + m*FST + c4*4) = v;
    }
    __syncthreads();

    unsigned Bh = sbase + OFF_HH;
    int q2 = (lane & 3) * 2, r = lane >> 2;
    int R0 = w*16 + r, R1 = R0 + 8;

    // ---- GEMM A+B fused: pos = d2*H, GH = G*H in one B sweep ----
    float accP[8][4], accG[8][4];
#pragma unroll
    for (int t=0;t<8;t++)
#pragma unroll
        for (int i=0;i<4;i++) { accP[t][i] = 0.f; accG[t][i] = 0.f; }
    gemm2_dual(&g_Wfr[0][0][w][0][0], &g_Wfr[0][1][w][0][0],
               &g_Wfr[1][0][w][0][0], &g_Wfr[1][1][w][0][0],
               Bh, accP, accG, lane);
#pragma unroll
    for (int t = 0; t < 8; t++) {
        int mA = (t>>1)*16 + (t&1)*8 + q2, mB = mA + 1;
        Ps[mA*FST+R0] = accP[t][0]; Ps[mB*FST+R0] = accP[t][1];
        Ps[mA*FST+R1] = accP[t][2]; Ps[mB*FST+R1] = accP[t][3];
    }
    __syncthreads();   // all warps done reading H before overwrite with T

    // T = relu(E - F + GH + c0) -> overwrite Hh (fp16)
    {
        float c00 = g_c0v[R0], c01 = g_c0v[R1];
#pragma unroll
        for (int t = 0; t < 8; t++) {
            int mA = (t>>1)*16 + (t&1)*8 + q2, mB = mA + 1;
            int pt = mA >> 4;
            float e0 = EsS[pt*128 + R0] + c00;
            float e1 = EsS[pt*128 + R1] + c01;
            Hh[mA*WST + R0] = __float2half(fmaxf(e0 - Fsm[mA*FST+R0] + accG[t][0], 0.f));
            Hh[mB*WST + R0] = __float2half(fmaxf(e0 - Fsm[mB*FST+R0] + accG[t][1], 0.f));
            Hh[mA*WST + R1] = __float2half(fmaxf(e1 - Fsm[mA*FST+R1] + accG[t][2], 0.f));
            Hh[mB*WST + R1] = __float2half(fmaxf(e1 - Fsm[mB*FST+R1] + accG[t][3], 0.f));
        }
    }
    __syncthreads();

    // alp gather (overwrites Fsm; overlapped with GEMM C) + GEMM C
    for (int q = tid; q < 2048; q += 256) {
        int m = q >> 5, c4 = q & 31;
        float4 v = *reinterpret_cast<const float4*>(g_alp + (bN + jb[m])*C_ + c4*4);
        *reinterpret_cast<float4*>(Fsm + m*FST + c4*4) = v;
    }
    float acc[8][4];
#pragma unroll
    for (int t=0;t<8;t++)
#pragma unroll
        for (int i=0;i<4;i++) acc[t][i] = 0.f;
    gemm2_sweep(&g_Wfr[2][0][w][0][0], &g_Wfr[2][1][w][0][0], Bh, acc, lane);
    __syncthreads();

    // softmax over k (16 per point) + aggregate; warp owns 4 pts x rows R0,R1
    {
        float g2b0 = g2B[R0], g2b1 = g2B[R1];
        float d2b0 = d2B[R0], d2b1 = d2B[R1];
#pragma unroll
        for (int pt = 0; pt < 4; pt++) {
            int t0 = 2*pt, t1 = t0 + 1;
            int m0 = pt*16 + q2, m2 = m0 + 8;
            {
                float a0 = acc[t0][0] + g2b0, a1 = acc[t0][1] + g2b0;
                float a2 = acc[t1][0] + g2b0, a3 = acc[t1][1] + g2b0;
                float mx = fmaxf(fmaxf(a0,a1), fmaxf(a2,a3));
                mx = fmaxf(mx, __shfl_xor_sync(FULLMASK, mx, 1));
                mx = fmaxf(mx, __shfl_xor_sync(FULLMASK, mx, 2));
                float e0=__expf(a0-mx), e1=__expf(a1-mx), e2=__expf(a2-mx), e3=__expf(a3-mx);
                float s = e0+e1+e2+e3;
                s += __shfl_xor_sync(FULLMASK, s, 1);
                s += __shfl_xor_sync(FULLMASK, s, 2);
                float num = e0*(Fsm[m0*FST+R0]     + Ps[m0*FST+R0]     + d2b0)
                          + e1*(Fsm[(m0+1)*FST+R0] + Ps[(m0+1)*FST+R0] + d2b0)
                          + e2*(Fsm[m2*FST+R0]     + Ps[m2*FST+R0]     + d2b0)
                          + e3*(Fsm[(m2+1)*FST+R0] + Ps[(m2+1)*FST+R0] + d2b0);
                num += __shfl_xor_sync(FULLMASK, num, 1);
                num += __shfl_xor_sync(FULLMASK, num, 2);
                if ((lane & 3) == 0) g_y[(bN + pt0 + pt)*C_ + R0] = num / s;
            }
            {
                float a0 = acc[t0][2] + g2b1, a1 = acc[t0][3] + g2b1;
                float a2 = acc[t1][2] + g2b1, a3 = acc[t1][3] + g2b1;
                float mx = fmaxf(fmaxf(a0,a1), fmaxf(a2,a3));
                mx = fmaxf(mx, __shfl_xor_sync(FULLMASK, mx, 1));
                mx = fmaxf(mx, __shfl_xor_sync(FULLMASK, mx, 2));
                float e0=__expf(a0-mx), e1=__expf(a1-mx), e2=__expf(a2-mx), e3=__expf(a3-mx);
                float s = e0+e1+e2+e3;
                s += __shfl_xor_sync(FULLMASK, s, 1);
                s += __shfl_xor_sync(FULLMASK, s, 2);
                float num = e0*(Fsm[m0*FST+R1]     + Ps[m0*FST+R1]     + d2b1)
                          + e1*(Fsm[(m0+1)*FST+R1] + Ps[(m0+1)*FST+R1] + d2b1)
                          + e2*(Fsm[m2*FST+R1]     + Ps[m2*FST+R1]     + d2b1)
                          + e3*(Fsm[(m2+1)*FST+R1] + Ps[(m2+1)*FST+R1] + d2b1);
                num += __shfl_xor_sync(FULLMASK, num, 1);
                num += __shfl_xor_sync(FULLMASK, num, 2);
                if ((lane & 3) == 0) g_y[(bN + pt0 + pt)*C_ + R1] = num / s;
            }
        }
    }
}

extern "C" void kernel_launch(void* const* d_in, const int* in_sizes, int n_in,
                              void* d_out, int out_size)
{
    const float* p    = (const float*)d_in[0];
    const float* x    = (const float*)d_in[1];
    const float* topW = (const float*)d_in[2];  const float* topB = (const float*)d_in[3];
    const float* dnW  = (const float*)d_in[4];  const float* dnB  = (const float*)d_in[5];
    const float* phiW = (const float*)d_in[6];  const float* phiB = (const float*)d_in[7];
    const float* psiW = (const float*)d_in[8];  const float* psiB = (const float*)d_in[9];
    const float* alW  = (const float*)d_in[10]; const float* alB  = (const float*)d_in[11];
    const float* g1W  = (const float*)d_in[12]; const float* g1B  = (const float*)d_in[13];
    const float* g2W  = (const float*)d_in[14]; const float* g2B  = (const float*)d_in[15];
    const float* d1W  = (const float*)d_in[16]; const float* d1B  = (const float*)d_in[17];
    const float* d2W  = (const float*)d_in[18]; const float* d2B  = (const float*)d_in[19];
    float* out = (float*)d_out;

    const int GP_SMEM = (128*LD_ + 16384) * 4;   // 133120
    cudaFuncSetAttribute(knn_kernel, cudaFuncAttributeMaxDynamicSharedMemorySize, 98304);
    cudaFuncSetAttribute(gemm_point<0>, cudaFuncAttributeMaxDynamicSharedMemorySize, GP_SMEM);
    cudaFuncSetAttribute(gemm_point<4>, cudaFuncAttributeMaxDynamicSharedMemorySize, GP_SMEM);
    cudaFuncSetAttribute(gemm_point123, cudaFuncAttributeMaxDynamicSharedMemorySize, GP_SMEM);
    cudaFuncSetAttribute(heavy_kernel, cudaFuncAttributeMaxDynamicSharedMemorySize, HEAVY_SMEM);

    // launch order chosen so heavy_kernel is launch index 5 (ncu -s 5 -c 1)
    prep_kernel<<<8, 256>>>(topW, phiW, psiW, alW, g2W, dnW, d2W, g1W,
                            phiB, psiB, d2B, g1B);                         // 0
    prep2_kernel<<<3, 256>>>(d2W, g2W);                                    // 1
    knn_kernel<<<dim3(N_/8, B_), 256, 98304>>>(p);                         // 2
    gemm_point<0><<<dim3(32, B_), 256, GP_SMEM>>>(topB, x, nullptr, nullptr); // 3
    gemm_point123<<<dim3(32, B_, 3), 256, GP_SMEM>>>(alB);                 // 4
    heavy_kernel<<<dim3(N_/4, B_), 256, HEAVY_SMEM>>>(p, d1W, d1B, d2B, g2B); // 5 <- profiled
    gemm_point<4><<<dim3(32, B_), 256, GP_SMEM>>>(dnB, nullptr, out, x);   // 6
}

// round 17
// speedup vs baseline: 1.3330x; 1.3330x over previous
#include <cuda_runtime.h>
#include <cuda_fp16.h>

#define FULLMASK 0xffffffffu
constexpr int B_ = 4, C_ = 128, N_ = 4096, K_ = 16;
constexpr int BN_ = B_ * N_;
constexpr int LD_ = 132;
constexpr int WST = 136;   // fp16 smem row stride (elems)
constexpr int FST = 132;   // fp32 smem row stride (elems)

__device__ float g_TE[C_*C_], g_TF[C_*C_], g_Tal[C_*C_], g_Tdn[C_*C_];
__device__ float g_bE[C_], g_bF[C_], g_bAl[C_], g_c0v[C_];
__device__ float g_E[BN_*C_];     // [B][N][C]
__device__ float g_F[BN_*C_];     // [B][N][C]
__device__ float g_alp[BN_*C_];   // [B][N][C]
__device__ float g_y[BN_*C_];     // [B][N][C]
__device__ int   g_idx[BN_*K_];
// MMA-fragment-layout fp16-split weights: [mat 0=d2,1=G,2=g2][hi/lo][co_tile][kstep][lane]
__device__ uint4 g_Wfr[3][2][8][8][32];

// ---------------- helpers ----------------
__device__ __forceinline__ unsigned smem_u32(const void* p) {
    unsigned a;
    asm("{ .reg .u64 t; cvta.to.shared.u64 t, %1; cvt.u32.u64 %0, t; }" : "=r"(a) : "l"(p));
    return a;
}
__device__ __forceinline__ void ldsm4(unsigned addr, unsigned r[4]) {
    asm volatile("ldmatrix.sync.aligned.m8n8.x4.shared.b16 {%0,%1,%2,%3}, [%4];"
        : "=r"(r[0]), "=r"(r[1]), "=r"(r[2]), "=r"(r[3]) : "r"(addr));
}
__device__ __forceinline__ void mma_f16(float c[4], unsigned a0, unsigned a1,
    unsigned a2, unsigned a3, unsigned b0, unsigned b1) {
    asm volatile("mma.sync.aligned.m16n8k16.row.col.f32.f16.f16.f32 "
        "{%0,%1,%2,%3},{%4,%5,%6,%7},{%8,%9},{%0,%1,%2,%3};"
        : "+f"(c[0]), "+f"(c[1]), "+f"(c[2]), "+f"(c[3])
        : "r"(a0), "r"(a1), "r"(a2), "r"(a3), "r"(b0), "r"(b1));
}
__device__ __forceinline__ unsigned short hfb(float v) {
    __half h = __float2half(v);
    return *reinterpret_cast<unsigned short*>(&h);
}

// 2-pass fp16 split sweep: acc[8][4] += W(16co x 128k) * B(64m x 128k)^T
__device__ __forceinline__ void gemm2_sweep(const uint4* __restrict__ Wh,
    const uint4* __restrict__ Wl, unsigned Bh, float acc[8][4], int lane)
{
    uint4 ah[8], al[8];
#pragma unroll
    for (int ks = 0; ks < 8; ks++) { ah[ks] = Wh[ks*32 + lane]; al[ks] = Wl[ks*32 + lane]; }
    int lr = lane & 7, sel = lane >> 3;
    int bro = lr + (((sel >> 1) & 1) << 3);
    int bco = (sel & 1) << 3;
#pragma unroll
    for (int ks = 0; ks < 8; ks++) {
        int k0 = ks * 16;
#pragma unroll
        for (int jp = 0; jp < 4; jp++) {
            unsigned boff = (unsigned)(((jp*16 + bro)*WST + bco + k0) << 1);
            unsigned bh[4];
            ldsm4(Bh + boff, bh);
            mma_f16(acc[2*jp],   ah[ks].x, ah[ks].y, ah[ks].z, ah[ks].w, bh[0], bh[1]);
            mma_f16(acc[2*jp+1], ah[ks].x, ah[ks].y, ah[ks].z, ah[ks].w, bh[2], bh[3]);
            mma_f16(acc[2*jp],   al[ks].x, al[ks].y, al[ks].z, al[ks].w, bh[0], bh[1]);
            mma_f16(acc[2*jp+1], al[ks].x, al[ks].y, al[ks].z, al[ks].w, bh[2], bh[3]);
        }
    }
}

// Dual 2-pass sweep: two weight matrices share each B-fragment load.
__device__ __forceinline__ void gemm2_dual(
    const uint4* __restrict__ W0h, const uint4* __restrict__ W0l,
    const uint4* __restrict__ W1h, const uint4* __restrict__ W1l,
    unsigned Bh, float accA[8][4], float accB[8][4], int lane)
{
    int lr = lane & 7, sel = lane >> 3;
    int bro = lr + (((sel >> 1) & 1) << 3);
    int bco = (sel & 1) << 3;
#pragma unroll
    for (int ks = 0; ks < 8; ks++) {
        uint4 a0 = W0h[ks*32 + lane], l0 = W0l[ks*32 + lane];
        uint4 a1 = W1h[ks*32 + lane], l1 = W1l[ks*32 + lane];
        int k0 = ks * 16;
#pragma unroll
        for (int jp = 0; jp < 4; jp++) {
            unsigned boff = (unsigned)(((jp*16 + bro)*WST + bco + k0) << 1);
            unsigned bh[4];
            ldsm4(Bh + boff, bh);
            mma_f16(accA[2*jp],   a0.x, a0.y, a0.z, a0.w, bh[0], bh[1]);
            mma_f16(accA[2*jp+1], a0.x, a0.y, a0.z, a0.w, bh[2], bh[3]);
            mma_f16(accB[2*jp],   a1.x, a1.y, a1.z, a1.w, bh[0], bh[1]);
            mma_f16(accB[2*jp+1], a1.x, a1.y, a1.z, a1.w, bh[2], bh[3]);
            mma_f16(accA[2*jp],   l0.x, l0.y, l0.z, l0.w, bh[0], bh[1]);
            mma_f16(accA[2*jp+1], l0.x, l0.y, l0.z, l0.w, bh[2], bh[3]);
            mma_f16(accB[2*jp],   l1.x, l1.y, l1.z, l1.w, bh[0], bh[1]);
            mma_f16(accB[2*jp+1], l1.x, l1.y, l1.z, l1.w, bh[2], bh[3]);
        }
    }
}

// ---- prep_all: one launch builds every derived weight ----
// blocks 0..23 : fused E/F/alpha weights (mat = b>>3, row-tile rt = b&7)
//   E_W = (g1@phi)@top, F_W = (g1@psi)@top, al_W = alW@top  (+ fused biases)
// block 24     : dn transpose
// block 25     : d2 fragments     block 34: g2 fragments
// blocks 26..33: G = g1@d2 row-tile -> fragments + c0v
__global__ __launch_bounds__(256) void prep_all(
    const float* __restrict__ topW, const float* __restrict__ topB,
    const float* __restrict__ phiW, const float* __restrict__ phiB,
    const float* __restrict__ psiW, const float* __restrict__ psiB,
    const float* __restrict__ alW,  const float* __restrict__ alB,
    const float* __restrict__ g1W,  const float* __restrict__ g1B,
    const float* __restrict__ d2W,  const float* __restrict__ d2B,
    const float* __restrict__ g2W,  const float* __restrict__ dnW)
{
    __shared__ float S[16*C_];
    int bid = blockIdx.x, tid = threadIdx.x;
    if (bid < 24) {
        int mat = bid >> 3, rt = bid & 7;
        const float* W1 = (mat==0)?phiW : psiW;
#pragma unroll
        for (int e = 0; e < 8; e++) {
            int q = tid + e*256;
            int r = q >> 7, m = q & 127;
            int co = rt*16 + r;
            float a;
            if (mat < 2) {
                float a0=0.f, a1=0.f;
                for (int k = 0; k < C_; k += 2) {
                    a0 = fmaf(g1W[co*C_+k],   W1[k*C_+m],     a0);
                    a1 = fmaf(g1W[co*C_+k+1], W1[(k+1)*C_+m], a1);
                }
                a = a0 + a1;
            } else {
                a = alW[co*C_+m];
            }
            S[r*C_+m] = a;
        }
        __syncthreads();
        float* dst = (mat==0)?g_TE : (mat==1)?g_TF : g_Tal;
#pragma unroll
        for (int e = 0; e < 8; e++) {
            int q = tid + e*256;
            int r = q >> 7, ci = q & 127;
            int co = rt*16 + r;
            float a0=0.f, a1=0.f;
            for (int m = 0; m < C_; m += 2) {
                a0 = fmaf(S[r*C_+m],   topW[m*C_+ci],     a0);
                a1 = fmaf(S[r*C_+m+1], topW[(m+1)*C_+ci], a1);
            }
            dst[ci*C_+co] = a0 + a1;
        }
        if (tid < 16) {
            int r = tid, co = rt*16 + r;
            float a = 0.f;
            for (int m = 0; m < C_; m++) a = fmaf(S[r*C_+m], topB[m], a);
            if (mat == 0) {
                for (int k = 0; k < C_; k++) a = fmaf(g1W[co*C_+k], phiB[k], a);
                g_bE[co] = a;
            } else if (mat == 1) {
                for (int k = 0; k < C_; k++) a = fmaf(g1W[co*C_+k], psiB[k], a);
                g_bF[co] = a;
            } else {
                g_bAl[co] = a + alB[co];
            }
        }
    } else if (bid == 24) {
        for (int q = tid; q < C_*C_; q += 256) {
            int co = q >> 7, ci = q & 127;
            g_Tdn[ci*C_+co] = dnW[co*C_+ci];
        }
    } else if (bid == 25 || bid == 34) {
        int mat = (bid == 25) ? 0 : 2;
        const float* src = (bid == 25) ? d2W : g2W;
        for (int q = tid; q < 2048; q += 256) {
            int t = q >> 8, ks = (q >> 5) & 7, lane = q & 31;
            int g = lane >> 2, c2 = (lane & 3) * 2;
            int r0 = t*16 + g, r1 = r0 + 8;
            int c0 = ks*16 + c2;
            unsigned hi[4], lo[4];
#pragma unroll
            for (int e = 0; e < 4; e++) {
                int rr = (e & 1) ? r1 : r0;
                int cb = c0 + ((e >> 1) << 3);
                float vA = src[rr*C_+cb], vB = src[rr*C_+cb+1];
                hi[e] = ((unsigned)hfb(vB) << 16) | (unsigned)hfb(vA);
                float ra = vA - __half2float(__float2half(vA));
                float rb2 = vB - __half2float(__float2half(vB));
                lo[e] = ((unsigned)hfb(rb2) << 16) | (unsigned)hfb(ra);
            }
            g_Wfr[mat][0][t][ks][lane] = make_uint4(hi[0], hi[1], hi[2], hi[3]);
            g_Wfr[mat][1][t][ks][lane] = make_uint4(lo[0], lo[1], lo[2], lo[3]);
        }
    } else {
        int t = bid - 26;            // G row-tile
#pragma unroll
        for (int e = 0; e < 8; e++) {
            int q = tid + e*256;
            int r = q >> 7, ci = q & 127;
            int co = t*16 + r;
            float a0=0.f, a1=0.f;
            for (int k = 0; k < C_; k += 2) {
                a0 = fmaf(g1W[co*C_+k],   d2W[k*C_+ci],     a0);
                a1 = fmaf(g1W[co*C_+k+1], d2W[(k+1)*C_+ci], a1);
            }
            S[r*C_+ci] = a0 + a1;
        }
        if (tid < 16) {
            int co = t*16 + tid;
            float a = 0.f;
            for (int k = 0; k < C_; k++) a = fmaf(g1W[co*C_+k], d2B[k], a);
            g_c0v[co] = a + g1B[co];
        }
        __syncthreads();
        {
            int ks = tid >> 5, lane = tid & 31;
            int g = lane >> 2, c2 = (lane & 3) * 2;
            int c0 = ks*16 + c2;
            unsigned hi[4], lo[4];
#pragma unroll
            for (int e = 0; e < 4; e++) {
                int rr = (e & 1) ? (g + 8) : g;       // local row
                int cb = c0 + ((e >> 1) << 3);
                float vA = S[rr*C_+cb], vB = S[rr*C_+cb+1];
                hi[e] = ((unsigned)hfb(vB) << 16) | (unsigned)hfb(vA);
                float ra = vA - __half2float(__float2half(vA));
                float rb2 = vB - __half2float(__float2half(vB));
                lo[e] = ((unsigned)hfb(rb2) << 16) | (unsigned)hfb(ra);
            }
            g_Wfr[1][0][t][ks][lane] = make_uint4(hi[0], hi[1], hi[2], hi[3]);
            g_Wfr[1][1][t][ks][lane] = make_uint4(lo[0], lo[1], lo[2], lo[3]);
        }
    }
}

// ---- KNN: 1 warp per query point ----
__global__ __launch_bounds__(256) void knn_kernel(const float* __restrict__ p)
{
    extern __shared__ float sm[];
    float* px = sm;      float* py = px + N_;
    float* pz = py + N_; float* sq = pz + N_;
    float* md = sq + N_;
    int*   mi = (int*)(md + 8*512);

    int b = blockIdx.y;
    const float* pb = p + (size_t)b*3*N_;
    for (int i = threadIdx.x; i < N_; i += 256) {
        float x = pb[i], y = pb[N_+i], z = pb[2*N_+i];
        px[i]=x; py[i]=y; pz[i]=z;
        sq[i] = __fadd_rn(__fadd_rn(__fmul_rn(x,x), __fmul_rn(y,y)), __fmul_rn(z,z));
    }
    __syncthreads();

    int warp = threadIdx.x >> 5, lane = threadIdx.x & 31;
    int n = blockIdx.x*8 + warp;
    float qx=px[n], qy=py[n], qz=pz[n], qs=sq[n];

    float bd[16]; int bi[16];
#pragma unroll
    for (int t=0;t<16;t++){ bd[t]=3.4e38f; bi[t]=0; }
    for (int c = lane; c < N_; c += 32) {
        float dot = __fadd_rn(__fadd_rn(__fmul_rn(qx,px[c]), __fmul_rn(qy,py[c])), __fmul_rn(qz,pz[c]));
        float d = __fadd_rn(__fadd_rn(qs, sq[c]), __fmul_rn(-2.f, dot));
        if (d < bd[15]) {
            bd[15]=d; bi[15]=c;
#pragma unroll
            for (int t=15;t>0;--t)
                if (bd[t] < bd[t-1]) {
                    float tf=bd[t]; bd[t]=bd[t-1]; bd[t-1]=tf;
                    int ti=bi[t]; bi[t]=bi[t-1]; bi[t-1]=ti;
                }
        }
    }
    float* wd = md + warp*512; int* wi = mi + warp*512;
#pragma unroll
    for (int t=0;t<16;t++){ wd[lane*16+t]=bd[t]; wi[lane*16+t]=bi[t]; }
    __syncwarp();

    int ptr = 0;
    int* outp = g_idx + ((size_t)b*N_ + n)*K_;
    for (int r = 0; r < K_; r++) {
        float cd = (ptr<16) ? wd[lane*16+ptr] : 3.4e38f;
        int   ci = (ptr<16) ? wi[lane*16+ptr] : 0;
        float mdv = cd; int miv = ci; int ml = lane;
#pragma unroll
        for (int off=16; off>0; off>>=1) {
            float od = __shfl_down_sync(FULLMASK, mdv, off);
            int   oi = __shfl_down_sync(FULLMASK, miv, off);
            int   ol = __shfl_down_sync(FULLMASK, ml,  off);
            if (od < mdv) { mdv=od; miv=oi; ml=ol; }
        }
        miv = __shfl_sync(FULLMASK, miv, 0);
        ml  = __shfl_sync(FULLMASK, ml, 0);
        if (lane == ml) ptr++;
        if (lane == 0) outp[r] = miv;
    }
}

// ---- fp32 GEMM fragment (weights in SMEM) ----
__device__ __forceinline__ void gemm_frag(const float* __restrict__ WT,
    const float* __restrict__ S, int c0, int m0, float acc[8][8])
{
#pragma unroll 4
    for (int ci = 0; ci < C_; ci++) {
        float4 a0 = *reinterpret_cast<const float4*>(WT + ci*C_ + c0);
        float4 a1 = *reinterpret_cast<const float4*>(WT + ci*C_ + c0 + 4);
        float4 b0 = *reinterpret_cast<const float4*>(S + ci*LD_ + m0);
        float4 b1 = *reinterpret_cast<const float4*>(S + ci*LD_ + m0 + 4);
        float av[8] = {a0.x,a0.y,a0.z,a0.w,a1.x,a1.y,a1.z,a1.w};
        float bv[8] = {b0.x,b0.y,b0.z,b0.w,b1.x,b1.y,b1.z,b1.w};
#pragma unroll
        for (int i=0;i<8;i++)
#pragma unroll
            for (int j=0;j<8;j++) acc[i][j] = fmaf(av[i], bv[j], acc[i][j]);
    }
}

// E/F/alpha direct from input_x: slot = blockIdx.z, out [B][N][C]
__global__ __launch_bounds__(256) void gemm_efa(const float* __restrict__ xin)
{
    extern __shared__ float Hs[];
    float* Ws = Hs + 128*LD_;
    int b = blockIdx.y, n0 = blockIdx.x*128, tid = threadIdx.x;
    int slot = blockIdx.z;
    const float* WT   = (slot==0)?g_TE : (slot==1)?g_TF : g_Tal;
    const float* bias = (slot==0)?g_bE : (slot==1)?g_bF : g_bAl;
    float* outp       = (slot==0)?g_E  : (slot==1)?g_F  : g_alp;

    for (int q = tid; q < 16384; q += 256) Ws[q] = WT[q];
    for (int q = tid; q < 4096; q += 256) {
        int ci = q >> 5, m4 = q & 31;
        float4 v = *reinterpret_cast<const float4*>(xin + ((size_t)(b*C_)+ci)*N_ + n0 + m4*4);
        *reinterpret_cast<float4*>(Hs + ci*LD_ + m4*4) = v;
    }
    __syncthreads();

    int tx = tid & 15, ty = tid >> 4;
    int m0 = tx*8, c0 = ty*8;
    float acc[8][8];
#pragma unroll
    for (int i=0;i<8;i++)
#pragma unroll
        for (int j=0;j<8;j++) acc[i][j] = 0.f;
    gemm_frag(Ws, Hs, c0, m0, acc);

    float bs[8];
#pragma unroll
    for (int i=0;i<8;i++) bs[i] = bias[c0+i];
#pragma unroll
    for (int j=0;j<8;j++) {
        int m = m0+j;
        float4 o0 = {acc[0][j]+bs[0], acc[1][j]+bs[1], acc[2][j]+bs[2], acc[3][j]+bs[3]};
        float4 o1 = {acc[4][j]+bs[4], acc[5][j]+bs[5], acc[6][j]+bs[6], acc[7][j]+bs[7]};
        *reinterpret_cast<float4*>(outp + ((size_t)(b*N_)+n0+m)*C_ + c0)     = o0;
        *reinterpret_cast<float4*>(outp + ((size_t)(b*N_)+n0+m)*C_ + c0 + 4) = o1;
    }
}

// down projection + residual: in g_y [B][N][C] -> out [B][C][N] + x
__global__ __launch_bounds__(256) void gemm_down(
    const float* __restrict__ bias, float* __restrict__ ext_out,
    const float* __restrict__ resid)
{
    extern __shared__ float Hs[];
    float* Ws = Hs + 128*LD_;
    int b = blockIdx.y, n0 = blockIdx.x*128, tid = threadIdx.x;

    for (int q = tid; q < 16384; q += 256) Ws[q] = g_Tdn[q];
    for (int q = tid; q < 4096; q += 256) {
        int m = q >> 5, c4 = q & 31;
        float4 v = *reinterpret_cast<const float4*>(g_y + ((size_t)(b*N_)+n0+m)*C_ + c4*4);
        int c = c4*4;
        Hs[(c+0)*LD_+m]=v.x; Hs[(c+1)*LD_+m]=v.y; Hs[(c+2)*LD_+m]=v.z; Hs[(c+3)*LD_+m]=v.w;
    }
    __syncthreads();

    int tx = tid & 15, ty = tid >> 4;
    int m0 = tx*8, c0 = ty*8;
    float acc[8][8];
#pragma unroll
    for (int i=0;i<8;i++)
#pragma unroll
        for (int j=0;j<8;j++) acc[i][j] = 0.f;
    gemm_frag(Ws, Hs, c0, m0, acc);

#pragma unroll
    for (int i=0;i<8;i++) {
        int c = c0+i;
        float bv = bias[c];
        float v[8];
        const float* r = resid + ((size_t)(b*C_)+c)*N_ + n0 + m0;
#pragma unroll
        for (int j=0;j<8;j++) v[j] = acc[i][j] + bv + r[j];
        float4 o0 = {v[0],v[1],v[2],v[3]}, o1 = {v[4],v[5],v[6],v[7]};
        *reinterpret_cast<float4*>(ext_out + ((size_t)(b*C_)+c)*N_ + n0 + m0)     = o0;
        *reinterpret_cast<float4*>(ext_out + ((size_t)(b*C_)+c)*N_ + n0 + m0 + 4) = o1;
    }
}

// ---- heavy kernel: 4 pts x 16 nbrs per CTA, 8 warps, 2 CTAs/SM ----
constexpr int OFF_HH = 0;                      // 64*WST*2 = 17408 (fp16 H/T)
constexpr int OFF_FS = 17408;                  // 64*FST*4 = 33792 (F, then alp)
constexpr int OFF_PS = 51200;                  // 33792 (pos)
constexpr int OFF_ES = 84992;                  // 4*128*4 = 2048
constexpr int OFF_RX = 87040;                  // 3*64*4
constexpr int OFF_JB = 87808;                  // 64*4
constexpr int HEAVY_SMEM = 88064;

__global__ __launch_bounds__(256, 2) void heavy_kernel(
    const float* __restrict__ p, const float* __restrict__ d1W,
    const float* __restrict__ d1B, const float* __restrict__ d2B,
    const float* __restrict__ g2B)
{
    extern __shared__ char smc[];
    unsigned sbase = smem_u32(smc);
    __half* Hh = (__half*)(smc + OFF_HH);
    float* Fsm = (float*)(smc + OFF_FS);
    float* Ps  = (float*)(smc + OFF_PS);
    float* EsS = (float*)(smc + OFF_ES);
    float* rx = (float*)(smc + OFF_RX);
    float* ry = rx + 64; float* rz = ry + 64;
    int*   jb = (int*)(smc + OFF_JB);

    int b = blockIdx.y, pt0 = blockIdx.x*4, tid = threadIdx.x;
    int lane = tid & 31, w = tid >> 5;
    size_t bN = (size_t)b * N_;

    const float* pb = p + (size_t)b*3*N_;
    if (tid < 64) {
        int m = tid, pt = m >> 4, n = pt0 + pt;
        int j = g_idx[(bN + n)*K_ + (m & 15)];
        jb[m] = j;
        rx[m] = pb[n]      - pb[j];
        ry[m] = pb[N_+n]   - pb[N_+j];
        rz[m] = pb[2*N_+n] - pb[2*N_+j];
    }
    for (int q = tid; q < 512; q += 256)
        EsS[q] = g_E[(bN + pt0 + (q >> 7))*C_ + (q & 127)];
    __syncthreads();

    // H build (single fp16) + F gather
    for (int q = tid; q < 8192; q += 256) {
        int m = q >> 7, ci = q & 127;
        float h = fmaf(d1W[ci*3+2], rz[m],
                  fmaf(d1W[ci*3+1], ry[m],
                  fmaf(d1W[ci*3+0], rx[m], d1B[ci])));
        Hh[m*WST + ci] = __float2half(fmaxf(h, 0.f));
    }
    for (int q = tid; q < 2048; q += 256) {
        int m = q >> 5, c4 = q & 31;
        float4 v = *reinterpret_cast<const float4*>(g_F + (bN + jb[m])*C_ + c4*4);
        *reinterpret_cast<float4*>(Fsm + m*FST + c4*4) = v;
    }
    __syncthreads();

    unsigned Bh = sbase + OFF_HH;
    int q2 = (lane & 3) * 2, r = lane >> 2;
    int R0 = w*16 + r, R1 = R0 + 8;

    // ---- GEMM A+B fused: pos = d2*H, GH = G*H in one B sweep ----
    float accP[8][4], accG[8][4];
#pragma unroll
    for (int t=0;t<8;t++)
#pragma unroll
        for (int i=0;i<4;i++) { accP[t][i] = 0.f; accG[t][i] = 0.f; }
    gemm2_dual(&g_Wfr[0][0][w][0][0], &g_Wfr[0][1][w][0][0],
               &g_Wfr[1][0][w][0][0], &g_Wfr[1][1][w][0][0],
               Bh, accP, accG, lane);
#pragma unroll
    for (int t = 0; t < 8; t++) {
        int mA = (t>>1)*16 + (t&1)*8 + q2, mB = mA + 1;
        Ps[mA*FST+R0] = accP[t][0]; Ps[mB*FST+R0] = accP[t][1];
        Ps[mA*FST+R1] = accP[t][2]; Ps[mB*FST+R1] = accP[t][3];
    }
    __syncthreads();   // all warps done reading H before overwrite with T

    // T = relu(E - F + GH + c0) -> overwrite Hh (fp16)
    {
        float c00 = g_c0v[R0], c01 = g_c0v[R1];
#pragma unroll
        for (int t = 0; t < 8; t++) {
            int mA = (t>>1)*16 + (t&1)*8 + q2, mB = mA + 1;
            int pt = mA >> 4;
            float e0 = EsS[pt*128 + R0] + c00;
            float e1 = EsS[pt*128 + R1] + c01;
            Hh[mA*WST + R0] = __float2half(fmaxf(e0 - Fsm[mA*FST+R0] + accG[t][0], 0.f));
            Hh[mB*WST + R0] = __float2half(fmaxf(e0 - Fsm[mB*FST+R0] + accG[t][1], 0.f));
            Hh[mA*WST + R1] = __float2half(fmaxf(e1 - Fsm[mA*FST+R1] + accG[t][2], 0.f));
            Hh[mB*WST + R1] = __float2half(fmaxf(e1 - Fsm[mB*FST+R1] + accG[t][3], 0.f));
        }
    }
    __syncthreads();

    // alp gather (overwrites Fsm; overlapped with GEMM C) + GEMM C
    for (int q = tid; q < 2048; q += 256) {
        int m = q >> 5, c4 = q & 31;
        float4 v = *reinterpret_cast<const float4*>(g_alp + (bN + jb[m])*C_ + c4*4);
        *reinterpret_cast<float4*>(Fsm + m*FST + c4*4) = v;
    }
    float acc[8][4];
#pragma unroll
    for (int t=0;t<8;t++)
#pragma unroll
        for (int i=0;i<4;i++) acc[t][i] = 0.f;
    gemm2_sweep(&g_Wfr[2][0][w][0][0], &g_Wfr[2][1][w][0][0], Bh, acc, lane);
    __syncthreads();

    // softmax over k (16 per point) + aggregate; warp owns 4 pts x rows R0,R1
    {
        float g2b0 = g2B[R0], g2b1 = g2B[R1];
        float d2b0 = d2B[R0], d2b1 = d2B[R1];
#pragma unroll
        for (int pt = 0; pt < 4; pt++) {
            int t0 = 2*pt, t1 = t0 + 1;
            int m0 = pt*16 + q2, m2 = m0 + 8;
            {
                float a0 = acc[t0][0] + g2b0, a1 = acc[t0][1] + g2b0;
                float a2 = acc[t1][0] + g2b0, a3 = acc[t1][1] + g2b0;
                float mx = fmaxf(fmaxf(a0,a1), fmaxf(a2,a3));
                mx = fmaxf(mx, __shfl_xor_sync(FULLMASK, mx, 1));
                mx = fmaxf(mx, __shfl_xor_sync(FULLMASK, mx, 2));
                float e0=__expf(a0-mx), e1=__expf(a1-mx), e2=__expf(a2-mx), e3=__expf(a3-mx);
                float s = e0+e1+e2+e3;
                s += __shfl_xor_sync(FULLMASK, s, 1);
                s += __shfl_xor_sync(FULLMASK, s, 2);
                float num = e0*(Fsm[m0*FST+R0]     + Ps[m0*FST+R0]     + d2b0)
                          + e1*(Fsm[(m0+1)*FST+R0] + Ps[(m0+1)*FST+R0] + d2b0)
                          + e2*(Fsm[m2*FST+R0]     + Ps[m2*FST+R0]     + d2b0)
                          + e3*(Fsm[(m2+1)*FST+R0] + Ps[(m2+1)*FST+R0] + d2b0);
                num += __shfl_xor_sync(FULLMASK, num, 1);
                num += __shfl_xor_sync(FULLMASK, num, 2);
                if ((lane & 3) == 0) g_y[(bN + pt0 + pt)*C_ + R0] = num / s;
            }
            {
                float a0 = acc[t0][2] + g2b1, a1 = acc[t0][3] + g2b1;
                float a2 = acc[t1][2] + g2b1, a3 = acc[t1][3] + g2b1;
                float mx = fmaxf(fmaxf(a0,a1), fmaxf(a2,a3));
                mx = fmaxf(mx, __shfl_xor_sync(FULLMASK, mx, 1));
                mx = fmaxf(mx, __shfl_xor_sync(FULLMASK, mx, 2));
                float e0=__expf(a0-mx), e1=__expf(a1-mx), e2=__expf(a2-mx), e3=__expf(a3-mx);
                float s = e0+e1+e2+e3;
                s += __shfl_xor_sync(FULLMASK, s, 1);
                s += __shfl_xor_sync(FULLMASK, s, 2);
                float num = e0*(Fsm[m0*FST+R1]     + Ps[m0*FST+R1]     + d2b1)
                          + e1*(Fsm[(m0+1)*FST+R1] + Ps[(m0+1)*FST+R1] + d2b1)
                          + e2*(Fsm[m2*FST+R1]     + Ps[m2*FST+R1]     + d2b1)
                          + e3*(Fsm[(m2+1)*FST+R1] + Ps[(m2+1)*FST+R1] + d2b1);
                num += __shfl_xor_sync(FULLMASK, num, 1);
                num += __shfl_xor_sync(FULLMASK, num, 2);
                if ((lane & 3) == 0) g_y[(bN + pt0 + pt)*C_ + R1] = num / s;
            }
        }
    }
}

extern "C" void kernel_launch(void* const* d_in, const int* in_sizes, int n_in,
                              void* d_out, int out_size)
{
    const float* p    = (const float*)d_in[0];
    const float* x    = (const float*)d_in[1];
    const float* topW = (const float*)d_in[2];  const float* topB = (const float*)d_in[3];
    const float* dnW  = (const float*)d_in[4];  const float* dnB  = (const float*)d_in[5];
    const float* phiW = (const float*)d_in[6];  const float* phiB = (const float*)d_in[7];
    const float* psiW = (const float*)d_in[8];  const float* psiB = (const float*)d_in[9];
    const float* alW  = (const float*)d_in[10]; const float* alB  = (const float*)d_in[11];
    const float* g1W  = (const float*)d_in[12]; const float* g1B  = (const float*)d_in[13];
    const float* g2W  = (const float*)d_in[14]; const float* g2B  = (const float*)d_in[15];
    const float* d1W  = (const float*)d_in[16]; const float* d1B  = (const float*)d_in[17];
    const float* d2W  = (const float*)d_in[18]; const float* d2B  = (const float*)d_in[19];
    float* out = (float*)d_out;

    const int GP_SMEM = (128*LD_ + 16384) * 4;   // 133120
    cudaFuncSetAttribute(knn_kernel, cudaFuncAttributeMaxDynamicSharedMemorySize, 98304);
    cudaFuncSetAttribute(gemm_efa, cudaFuncAttributeMaxDynamicSharedMemorySize, GP_SMEM);
    cudaFuncSetAttribute(gemm_down, cudaFuncAttributeMaxDynamicSharedMemorySize, GP_SMEM);
    cudaFuncSetAttribute(heavy_kernel, cudaFuncAttributeMaxDynamicSharedMemorySize, HEAVY_SMEM);

    prep_all<<<35, 256>>>(topW, topB, phiW, phiB, psiW, psiB, alW, alB,
                          g1W, g1B, d2W, d2B, g2W, dnW);                   // 0
    knn_kernel<<<dim3(N_/8, B_), 256, 98304>>>(p);                         // 1
    gemm_efa<<<dim3(32, B_, 3), 256, GP_SMEM>>>(x);                        // 2
    heavy_kernel<<<dim3(N_/4, B_), 256, HEAVY_SMEM>>>(p, d1W, d1B, d2B, g2B); // 3 <- global 5
    gemm_down<<<dim3(32, B_), 256, GP_SMEM>>>(dnB, out, x);                // 4
}